// round 6
// baseline (speedup 1.0000x reference)
#include <cuda_runtime.h>
#include <cuda_bf16.h>

// Problem constants: b=4, t=10, h=w=256, dim_ae=32
#define HH 256
#define WW 256
#define HW (HH * WW)

// Scratch (allocation-free rule: __device__ globals)
__device__ float g_p1[4 * 32 * HW];   // conv1 out
__device__ float g_p2[4 * 64 * HW];   // conv2 out
__device__ float g_pm[4 * 60 * HW];   // conv3 out (params)

// ---- packed f32x2 helpers (sm_100+ PTX) -----------------------------------
__device__ __forceinline__ unsigned long long pk2(float lo, float hi) {
    unsigned long long r;
    asm("mov.b64 %0, {%1,%2};" : "=l"(r) : "f"(lo), "f"(hi));
    return r;
}
__device__ __forceinline__ void unpk2(unsigned long long v, float& lo, float& hi) {
    asm("mov.b64 {%0,%1}, %2;" : "=f"(lo), "=f"(hi) : "l"(v));
}
__device__ __forceinline__ void fma2(unsigned long long& acc, unsigned long long w,
                                     unsigned long long x) {
    asm("fma.rn.f32x2 %0, %1, %2, %0;" : "+l"(acc) : "l"(w), "l"(x));
}

// ---------------------------------------------------------------------------
// Direct 3x3 SAME conv, NCHW, packed-f32x2 math.
// Block = 16x16 threads -> 32x32 spatial tile, 16 output channels per block.
// Each thread: 2 rows x (1 f32x2 = 2 cols) x 16 couts.
// Weights live in smem DUPLICATED into 8-byte pairs so one broadcast LDS.64
// yields the packed multiplier. Input pairs (r0,r1),(r2,r3) are aligned
// LDS.64; middle pair (r1,r2) is one register repack.
// ---------------------------------------------------------------------------
template <int CIN, int COUT, bool RELU>
__global__ __launch_bounds__(256, 2)
void conv3x3_kernel(const float* __restrict__ in, const float* __restrict__ wt,
                    float* __restrict__ out) {
    constexpr int CT = 16;            // couts per block
    constexpr int CC = 4;             // cin chunk
    constexpr int TS = 32;            // spatial tile
    constexpr int IT = TS + 2;        // 34 (haloed)
    constexpr int BPC = (COUT + CT - 1) / CT;

    __shared__ float s_in[CC][IT][IT];                 // rows 8B-aligned (34 even)
    __shared__ unsigned long long s_w[CT][CC][9];      // duplicated weight pairs

    const int tx = threadIdx.x, ty = threadIdx.y;
    const int tid = ty * 16 + tx;
    const int bx = blockIdx.x * TS, by = blockIdx.y * TS;
    const int cob = (blockIdx.z % BPC) * CT;
    const int n = blockIdx.z / BPC;

    const float* in_n = in + (size_t)n * CIN * HW;

    unsigned long long acc[CT][2];
#pragma unroll
    for (int c = 0; c < CT; c++) { acc[c][0] = 0ull; acc[c][1] = 0ull; }

    for (int c0 = 0; c0 < CIN; c0 += CC) {
        __syncthreads();
        // weights for this chunk, duplicated into both f32x2 lanes
        for (int i = tid; i < CT * CC * 9; i += 256) {
            int ct = i / (CC * 9);
            int rem = i - ct * (CC * 9);
            int cc = rem / 9, k = rem - cc * 9;
            int co = cob + ct, ci = c0 + cc;
            float v = 0.f;
            if (co < COUT && ci < CIN) v = wt[((size_t)co * CIN + ci) * 9 + k];
            s_w[ct][cc][k] = pk2(v, v);
        }
        // haloed input tile (zero padding + zero-fill extra cin)
        for (int i = tid; i < CC * IT * IT; i += 256) {
            int cc = i / (IT * IT);
            int rem = i - cc * (IT * IT);
            int r = rem / IT, cl = rem - r * IT;
            int ci = c0 + cc;
            int gy = by + r - 1, gx = bx + cl - 1;
            float v = 0.f;
            if (ci < CIN && (unsigned)gy < HH && (unsigned)gx < WW) {
                v = in_n[(size_t)ci * HW + gy * WW + gx];
                if (RELU) v = fmaxf(v, 0.f);
            }
            s_in[cc][r][cl] = v;
        }
        __syncthreads();

#pragma unroll
        for (int cc = 0; cc < CC; cc++) {
            // packed input pairs: P[row][dx] = (r[dx], r[dx+1]) for dx 0..2
            unsigned long long P[4][3];
#pragma unroll
            for (int i = 0; i < 4; i++) {
                const float* rp = &s_in[cc][ty * 2 + i][tx * 2];
                unsigned long long A = *(const unsigned long long*)rp;       // r0,r1
                unsigned long long B = *(const unsigned long long*)(rp + 2); // r2,r3
                float a0, a1, b0, b1;
                unpk2(A, a0, a1);
                unpk2(B, b0, b1);
                P[i][0] = A;
                P[i][1] = pk2(a1, b0);  // r1,r2
                P[i][2] = B;
            }
#pragma unroll
            for (int ct = 0; ct < CT; ct++) {
                unsigned long long wp[9];
#pragma unroll
                for (int k = 0; k < 9; k++) wp[k] = s_w[ct][cc][k];
#pragma unroll
                for (int dy = 0; dy < 3; dy++)
#pragma unroll
                    for (int dx = 0; dx < 3; dx++) {
                        fma2(acc[ct][0], wp[dy * 3 + dx], P[dy][dx]);
                        fma2(acc[ct][1], wp[dy * 3 + dx], P[dy + 1][dx]);
                    }
            }
        }
    }

    const int oy = by + ty * 2, ox = bx + tx * 2;
#pragma unroll
    for (int ct = 0; ct < CT; ct++) {
        int co = cob + ct;
        if (co < COUT) {
            float* op = out + ((size_t)n * COUT + co) * HW + (size_t)oy * WW + ox;
            float l0, h0, l1, h1;
            unpk2(acc[ct][0], l0, h0);
            unpk2(acc[ct][1], l1, h1);
            *(float2*)op = make_float2(l0, h0);
            *(float2*)(op + WW) = make_float2(l1, h1);
        }
    }
}

// ---------------------------------------------------------------------------
// Fused guide/PAC epilogue (unchanged from R1; 25us, not the bottleneck).
// ---------------------------------------------------------------------------
__device__ __forceinline__ float softplus10(float p) {
    float z = 10.f * p;
    return (fmaxf(z, 0.f) + log1pf(__expf(-fabsf(z)))) * 0.1f;
}

__global__ __launch_bounds__(256)
void fuse_kernel(const float* __restrict__ x, const float* __restrict__ params,
                 const float* __restrict__ pw, const float* __restrict__ pb,
                 float* __restrict__ out) {
    const int gx = blockIdx.x * 32 + threadIdx.x;
    const int gy = blockIdx.y * 8 + threadIdx.y;
    const int z = blockIdx.z;
    const int j = z % 10, n = z / 10;
    const size_t opix = (((size_t)n * 10 + j) * HH + gy) * WW + gx;
    if (j == 9) { out[opix] = 0.f; return; }
    const int t = j + 1;

    const float* pbase = params + (size_t)n * 60 * HW + (size_t)gy * WW + gx;
    const float kap = softplus10(pbase[(size_t)(t) * HW]);
    const float m1d = pbase[(size_t)(10 + t) * HW];
    const float m2d = pbase[(size_t)(20 + t) * HW];
    const float gam = softplus10(pbase[(size_t)(30 + t) * HW]);
    const float vx = pbase[(size_t)(40 + t) * HW];
    const float vy = pbase[(size_t)(50 + t) * HW];

    const float H11 = gam + vx * vx;
    const float H22 = gam + vy * vy;
    const float H12 = vx * vy;
    const float iH11 = 1.f / H11;
    const float iH22 = 1.f / H22;

    float wk[9];
    wk[0] = -0.5f * H12;
    wk[1] = -iH22 + m1d;
    wk[2] = 0.5f * H12;
    wk[3] = -iH11 - m2d;
    wk[4] = kap + 2.f * H11 + 2.f * H22 + 1.f;
    wk[5] = -iH11 + m2d;
    wk[6] = 0.5f * H12;
    wk[7] = -iH22 - m1d;
    wk[8] = -0.5f * H12;

    const float* xf = x + ((size_t)n * 10 + t) * HW;
    float s = 0.f;
#pragma unroll
    for (int d = 0; d < 3; d++)
#pragma unroll
        for (int e = 0; e < 3; e++) {
            const int yy = gy + d - 1, xx = gx + e - 1;
            float xv = 0.f;
            if ((unsigned)yy < HH && (unsigned)xx < WW) xv = __ldg(xf + (size_t)yy * WW + xx);
            s = fmaf(__ldg(pw + d * 3 + e) * wk[d * 3 + e], xv, s);
        }
    out[opix] = s + __ldg(pb);
}

extern "C" void kernel_launch(void* const* d_in, const int* in_sizes, int n_in,
                              void* d_out, int out_size) {
    (void)in_sizes; (void)n_in; (void)out_size;
    const float* x  = (const float*)d_in[0];
    const float* w1 = (const float*)d_in[1];
    const float* w2 = (const float*)d_in[2];
    const float* w3 = (const float*)d_in[3];
    const float* pw = (const float*)d_in[4];
    const float* pb = (const float*)d_in[5];
    float* out = (float*)d_out;

    float *p1, *p2, *pm;
    cudaGetSymbolAddress((void**)&p1, g_p1);
    cudaGetSymbolAddress((void**)&p2, g_p2);
    cudaGetSymbolAddress((void**)&pm, g_pm);

    const dim3 blk(16, 16);
    // conv1: 10 -> 32 (relu on input), 2 cout-blocks per image
    conv3x3_kernel<10, 32, true><<<dim3(8, 8, 4 * 2), blk>>>(x, w1, p1);
    // conv2: 32 -> 64 (relu on input), 4 cout-blocks
    conv3x3_kernel<32, 64, true><<<dim3(8, 8, 4 * 4), blk>>>(p1, w2, p2);
    // conv3: 64 -> 60 (no relu), ceil(60/16)=4 cout-blocks
    conv3x3_kernel<64, 60, false><<<dim3(8, 8, 4 * 4), blk>>>(p2, w3, pm);
    // fused guide + PAC epilogue (also zeroes frame 9)
    fuse_kernel<<<dim3(8, 32, 40), dim3(32, 8)>>>(x, pm, pw, pb, out);
}

// round 10
// speedup vs baseline: 1.4413x; 1.4413x over previous
#include <cuda_runtime.h>
#include <cuda_bf16.h>
#include <cstdint>

#define HH 256
#define WW 256
#define HW (HH * WW)

// Scratch (allocation-free rule: __device__ globals)
__device__ float g_p1[4 * 32 * HW];       // conv1 out
__device__ float g_p2[4 * 64 * HW];       // conv2 out
__device__ float g_pm[4 * 60 * HW];       // conv3 out (params)
__device__ float g_wB2[9 * 32 * 64];      // conv2 weights [c][kk][co]
__device__ float g_wB3[18 * 32 * 64];     // conv3 weights [c][kk][co]

// ---- tf32 helpers (non-arch-specific PTX, sm_80+) --------------------------
__device__ __forceinline__ unsigned tf32r(float v) {
    unsigned u;
    asm("cvt.rna.tf32.f32 %0, %1;" : "=r"(u) : "f"(v));
    return u;
}
__device__ __forceinline__ void split_tf32(float v, float& hi, float& lo) {
    unsigned h = tf32r(v);
    float hf = __uint_as_float(h);
    unsigned l = tf32r(v - hf);
    hi = hf;
    lo = __uint_as_float(l);
}
__device__ __forceinline__ void mma_tf32(float* d, const unsigned* a, const unsigned* b) {
    asm volatile(
        "mma.sync.aligned.m16n8k8.row.col.f32.tf32.tf32.f32 "
        "{%0,%1,%2,%3}, {%4,%5,%6,%7}, {%8,%9}, {%0,%1,%2,%3};"
        : "+f"(d[0]), "+f"(d[1]), "+f"(d[2]), "+f"(d[3])
        : "r"(a[0]), "r"(a[1]), "r"(a[2]), "r"(a[3]), "r"(b[0]), "r"(b[1]));
}

// ---------------------------------------------------------------------------
// Weight reorder: wt[cout][cin][9] -> out[c=j*G+g][kk(32)][co(64)]  (fp32)
// ---------------------------------------------------------------------------
__global__ void reorder_w(const float* __restrict__ wt, float* __restrict__ out,
                          int CIN, int COUT, int G) {
    int i = blockIdx.x * 256 + threadIdx.x;
    int total = 9 * G * 32 * 64;
    if (i >= total) return;
    int co = i & 63, kk = (i >> 6) & 31, c = i >> 11;
    int j = c / G, g = c % G;
    int ci = g * 32 + kk;
    float v = 0.f;
    if (co < COUT && ci < CIN) v = wt[((size_t)co * CIN + ci) * 9 + j];
    out[i] = v;
}

// ---------------------------------------------------------------------------
// 3xTF32 mma.sync implicit-GEMM 3x3 conv.
// CTA: 128px row-strip (image n, row y) x 64 couts, 256 thr = 8 warps,
// warp(w): px block (w&3)*32, cout block (w>>2)*32 -> 2x4 m16n8 tiles.
// K = cin*9 in chunks of 32 (3x3 offset j x 32-cin group g).
// SMEM: A hi/lo [32][136] fp32-as-tf32, B hi/lo [32][72]. Conflict-free
// fragment LDS: bank = (8t+g)%32 bijective over the warp.
// 3 passes per chunk: Ah*Bh, Al*Bh (shares Bh frags), Ah*Bl.
// ---------------------------------------------------------------------------
#define SA_STR 136
#define SB_STR 72
#define CONV_SMEM (2 * (32 * SA_STR + 32 * SB_STR) * 4)  // 53248 B

template <int CIN, int COUT, bool RELU>
__global__ __launch_bounds__(256, 2)
void conv_tc(const float* __restrict__ in, const float* __restrict__ wB,
             float* __restrict__ out) {
    constexpr int G = CIN / 32;
    constexpr int NCH = 9 * G;
    extern __shared__ float sm[];
    float* s_ah = sm;                        // 32*136
    float* s_al = sm + 32 * SA_STR;          // 32*136
    float* s_bh = sm + 64 * SA_STR;          // 32*72
    float* s_bl = sm + 64 * SA_STR + 32 * SB_STR;

    const int tid = threadIdx.x;
    const int wid = tid >> 5, lane = tid & 31;
    const int g = lane >> 2, t = lane & 3;
    const int pxb = (wid & 3) * 32;
    const int cob = (wid >> 2) * 32;
    const int x0 = blockIdx.x * 128, y = blockIdx.y, n = blockIdx.z;
    const float* in_n = in + (size_t)n * CIN * HW;

    float acc[2][4][4];
#pragma unroll
    for (int mt = 0; mt < 2; mt++)
#pragma unroll
        for (int nt = 0; nt < 4; nt++)
#pragma unroll
            for (int e = 0; e < 4; e++) acc[mt][nt][e] = 0.f;

    // prefetch mappings
    const int pk = tid >> 3;        // 0..31 : k-row for A / kk-row for B
    const int pl = tid & 7;         // A: px = pl + 8i ; B: co0 = pl*8

    float regA[16];
    float regB[8];

    auto loadA = [&](int c) {
        const int j = c / G, gg = c % G;
        const int dy = j / 3 - 1, dx = j % 3 - 1;
        const int yg = y + dy;
        const bool yok = (unsigned)yg < HH;
        const float* src = in_n + ((size_t)(gg * 32 + pk)) * HW + (size_t)(yok ? yg : 0) * WW;
#pragma unroll
        for (int i = 0; i < 16; i++) {
            const int xg = x0 + pl + 8 * i + dx;
            float v = 0.f;
            if (yok && (unsigned)xg < WW) {
                v = __ldg(src + xg);
                if (RELU) v = fmaxf(v, 0.f);
            }
            regA[i] = v;
        }
    };
    auto loadB = [&](int c) {
        const float4* p = (const float4*)(wB + (size_t)c * 2048 + pk * 64 + pl * 8);
        float4 v0 = __ldg(p), v1 = __ldg(p + 1);
        regB[0] = v0.x; regB[1] = v0.y; regB[2] = v0.z; regB[3] = v0.w;
        regB[4] = v1.x; regB[5] = v1.y; regB[6] = v1.z; regB[7] = v1.w;
    };
    auto storeAB = [&]() {
#pragma unroll
        for (int i = 0; i < 16; i++) {
            float hi, lo;
            split_tf32(regA[i], hi, lo);
            s_ah[pk * SA_STR + pl + 8 * i] = hi;
            s_al[pk * SA_STR + pl + 8 * i] = lo;
        }
#pragma unroll
        for (int i = 0; i < 8; i++) {
            float hi, lo;
            split_tf32(regB[i], hi, lo);
            s_bh[pk * SB_STR + pl * 8 + i] = hi;
            s_bl[pk * SB_STR + pl * 8 + i] = lo;
        }
    };

    loadA(0);
    loadB(0);

    for (int c = 0; c < NCH; c++) {
        __syncthreads();   // previous chunk's consumers done
        storeAB();
        __syncthreads();
        if (c + 1 < NCH) { loadA(c + 1); loadB(c + 1); }

        const unsigned* uah = (const unsigned*)s_ah;
        const unsigned* ual = (const unsigned*)s_al;
        const unsigned* ubh = (const unsigned*)s_bh;
        const unsigned* ubl = (const unsigned*)s_bl;

#pragma unroll
        for (int ks = 0; ks < 4; ks++) {
            const int kb = ks * 8;
            unsigned bh[4][2], ah[2][4];
#pragma unroll
            for (int nt = 0; nt < 4; nt++) {
                const int co = cob + nt * 8 + g;
                bh[nt][0] = ubh[(kb + t) * SB_STR + co];
                bh[nt][1] = ubh[(kb + t + 4) * SB_STR + co];
            }
#pragma unroll
            for (int mt = 0; mt < 2; mt++) {
                const int px = pxb + mt * 16 + g;
                ah[mt][0] = uah[(kb + t) * SA_STR + px];
                ah[mt][1] = uah[(kb + t) * SA_STR + px + 8];
                ah[mt][2] = uah[(kb + t + 4) * SA_STR + px];
                ah[mt][3] = uah[(kb + t + 4) * SA_STR + px + 8];
            }
#pragma unroll
            for (int mt = 0; mt < 2; mt++)
#pragma unroll
                for (int nt = 0; nt < 4; nt++) mma_tf32(acc[mt][nt], ah[mt], bh[nt]);

            unsigned al[2][4];
#pragma unroll
            for (int mt = 0; mt < 2; mt++) {
                const int px = pxb + mt * 16 + g;
                al[mt][0] = ual[(kb + t) * SA_STR + px];
                al[mt][1] = ual[(kb + t) * SA_STR + px + 8];
                al[mt][2] = ual[(kb + t + 4) * SA_STR + px];
                al[mt][3] = ual[(kb + t + 4) * SA_STR + px + 8];
            }
#pragma unroll
            for (int mt = 0; mt < 2; mt++)
#pragma unroll
                for (int nt = 0; nt < 4; nt++) mma_tf32(acc[mt][nt], al[mt], bh[nt]);
        }
        // pass 3: Ah * Bl
#pragma unroll
        for (int ks = 0; ks < 4; ks++) {
            const int kb = ks * 8;
            unsigned bl[4][2], ah[2][4];
#pragma unroll
            for (int nt = 0; nt < 4; nt++) {
                const int co = cob + nt * 8 + g;
                bl[nt][0] = ubl[(kb + t) * SB_STR + co];
                bl[nt][1] = ubl[(kb + t + 4) * SB_STR + co];
            }
#pragma unroll
            for (int mt = 0; mt < 2; mt++) {
                const int px = pxb + mt * 16 + g;
                ah[mt][0] = uah[(kb + t) * SA_STR + px];
                ah[mt][1] = uah[(kb + t) * SA_STR + px + 8];
                ah[mt][2] = uah[(kb + t + 4) * SA_STR + px];
                ah[mt][3] = uah[(kb + t + 4) * SA_STR + px + 8];
            }
#pragma unroll
            for (int mt = 0; mt < 2; mt++)
#pragma unroll
                for (int nt = 0; nt < 4; nt++) mma_tf32(acc[mt][nt], ah[mt], bl[nt]);
        }
    }

    // scatter store: per STG.32, 32 lanes hit 4 fully-covered 32B sectors
    float* out_n = out + (size_t)n * COUT * HW + (size_t)y * WW + x0;
#pragma unroll
    for (int mt = 0; mt < 2; mt++)
#pragma unroll
        for (int nt = 0; nt < 4; nt++)
#pragma unroll
            for (int e = 0; e < 4; e++) {
                const int px = pxb + mt * 16 + g + ((e >> 1) & 1) * 8;
                const int co = cob + nt * 8 + 2 * t + (e & 1);
                if (co < COUT) out_n[(size_t)co * HW + px] = acc[mt][nt][e];
            }
}

// ---------------------------------------------------------------------------
// conv1 (10 -> 32): scalar fp32 direct conv
// ---------------------------------------------------------------------------
template <int CIN, int COUT, bool RELU>
__global__ __launch_bounds__(256, 2)
void conv3x3_kernel(const float* __restrict__ in, const float* __restrict__ wt,
                    float* __restrict__ out) {
    constexpr int CT = 16, CC = 4, TS = 32, IT = TS + 2;
    constexpr int BPC = (COUT + CT - 1) / CT;
    __shared__ float s_in[CC][IT][IT];
    __shared__ float s_w[CT][CC][9];
    const int tx = threadIdx.x, ty = threadIdx.y;
    const int tid = ty * 16 + tx;
    const int bx = blockIdx.x * TS, by = blockIdx.y * TS;
    const int cob = (blockIdx.z % BPC) * CT;
    const int n = blockIdx.z / BPC;
    const float* in_n = in + (size_t)n * CIN * HW;
    float acc[CT][2][2];
#pragma unroll
    for (int c = 0; c < CT; c++)
#pragma unroll
        for (int i = 0; i < 2; i++)
#pragma unroll
            for (int jj = 0; jj < 2; jj++) acc[c][i][jj] = 0.f;
    for (int c0 = 0; c0 < CIN; c0 += CC) {
        __syncthreads();
        for (int i = tid; i < CT * CC * 9; i += 256) {
            int ct = i / (CC * 9), rem = i - ct * (CC * 9);
            int cc = rem / 9, k = rem - cc * 9;
            int co = cob + ct, ci = c0 + cc;
            float v = 0.f;
            if (co < COUT && ci < CIN) v = wt[((size_t)co * CIN + ci) * 9 + k];
            s_w[ct][cc][k] = v;
        }
        for (int i = tid; i < CC * IT * IT; i += 256) {
            int cc = i / (IT * IT), rem = i - cc * (IT * IT);
            int r = rem / IT, cl = rem - r * IT;
            int ci = c0 + cc;
            int gy = by + r - 1, gx = bx + cl - 1;
            float v = 0.f;
            if (ci < CIN && (unsigned)gy < HH && (unsigned)gx < WW) {
                v = in_n[(size_t)ci * HW + gy * WW + gx];
                if (RELU) v = fmaxf(v, 0.f);
            }
            s_in[cc][r][cl] = v;
        }
        __syncthreads();
#pragma unroll
        for (int cc = 0; cc < CC; cc++) {
            float r[4][4];
#pragma unroll
            for (int i = 0; i < 4; i++)
#pragma unroll
                for (int jj = 0; jj < 4; jj++) r[i][jj] = s_in[cc][ty * 2 + i][tx * 2 + jj];
#pragma unroll
            for (int ct = 0; ct < CT; ct++) {
                float wk[9];
#pragma unroll
                for (int k = 0; k < 9; k++) wk[k] = s_w[ct][cc][k];
#pragma unroll
                for (int dy = 0; dy < 3; dy++)
#pragma unroll
                    for (int dx = 0; dx < 3; dx++) {
                        const float wv = wk[dy * 3 + dx];
                        acc[ct][0][0] = fmaf(wv, r[dy][dx], acc[ct][0][0]);
                        acc[ct][0][1] = fmaf(wv, r[dy][dx + 1], acc[ct][0][1]);
                        acc[ct][1][0] = fmaf(wv, r[dy + 1][dx], acc[ct][1][0]);
                        acc[ct][1][1] = fmaf(wv, r[dy + 1][dx + 1], acc[ct][1][1]);
                    }
            }
        }
    }
    const int oy = by + ty * 2, ox = bx + tx * 2;
#pragma unroll
    for (int ct = 0; ct < CT; ct++) {
        int co = cob + ct;
        if (co < COUT) {
            float* op = out + ((size_t)n * COUT + co) * HW + (size_t)oy * WW + ox;
            op[0] = acc[ct][0][0];
            op[1] = acc[ct][0][1];
            op[WW] = acc[ct][1][0];
            op[WW + 1] = acc[ct][1][1];
        }
    }
}

// ---------------------------------------------------------------------------
// Fused guide/PAC epilogue (unchanged)
// ---------------------------------------------------------------------------
__device__ __forceinline__ float softplus10(float p) {
    float z = 10.f * p;
    return (fmaxf(z, 0.f) + log1pf(__expf(-fabsf(z)))) * 0.1f;
}

__global__ __launch_bounds__(256)
void fuse_kernel(const float* __restrict__ x, const float* __restrict__ params,
                 const float* __restrict__ pw, const float* __restrict__ pb,
                 float* __restrict__ out) {
    const int gx = blockIdx.x * 32 + threadIdx.x;
    const int gy = blockIdx.y * 8 + threadIdx.y;
    const int z = blockIdx.z;
    const int j = z % 10, n = z / 10;
    const size_t opix = (((size_t)n * 10 + j) * HH + gy) * WW + gx;
    if (j == 9) { out[opix] = 0.f; return; }
    const int t = j + 1;
    const float* pbase = params + (size_t)n * 60 * HW + (size_t)gy * WW + gx;
    const float kap = softplus10(pbase[(size_t)(t) * HW]);
    const float m1d = pbase[(size_t)(10 + t) * HW];
    const float m2d = pbase[(size_t)(20 + t) * HW];
    const float gam = softplus10(pbase[(size_t)(30 + t) * HW]);
    const float vx = pbase[(size_t)(40 + t) * HW];
    const float vy = pbase[(size_t)(50 + t) * HW];
    const float H11 = gam + vx * vx;
    const float H22 = gam + vy * vy;
    const float H12 = vx * vy;
    const float iH11 = 1.f / H11;
    const float iH22 = 1.f / H22;
    float wk[9];
    wk[0] = -0.5f * H12;
    wk[1] = -iH22 + m1d;
    wk[2] = 0.5f * H12;
    wk[3] = -iH11 - m2d;
    wk[4] = kap + 2.f * H11 + 2.f * H22 + 1.f;
    wk[5] = -iH11 + m2d;
    wk[6] = 0.5f * H12;
    wk[7] = -iH22 - m1d;
    wk[8] = -0.5f * H12;
    const float* xf = x + ((size_t)n * 10 + t) * HW;
    float s = 0.f;
#pragma unroll
    for (int d = 0; d < 3; d++)
#pragma unroll
        for (int e = 0; e < 3; e++) {
            const int yy = gy + d - 1, xx = gx + e - 1;
            float xv = 0.f;
            if ((unsigned)yy < HH && (unsigned)xx < WW) xv = __ldg(xf + (size_t)yy * WW + xx);
            s = fmaf(__ldg(pw + d * 3 + e) * wk[d * 3 + e], xv, s);
        }
    out[opix] = s + __ldg(pb);
}

extern "C" void kernel_launch(void* const* d_in, const int* in_sizes, int n_in,
                              void* d_out, int out_size) {
    (void)in_sizes; (void)n_in; (void)out_size;
    const float* x  = (const float*)d_in[0];
    const float* w1 = (const float*)d_in[1];
    const float* w2 = (const float*)d_in[2];
    const float* w3 = (const float*)d_in[3];
    const float* pw = (const float*)d_in[4];
    const float* pb = (const float*)d_in[5];
    float* out = (float*)d_out;

    float *p1, *p2, *pm, *wB2, *wB3;
    cudaGetSymbolAddress((void**)&p1, g_p1);
    cudaGetSymbolAddress((void**)&p2, g_p2);
    cudaGetSymbolAddress((void**)&pm, g_pm);
    cudaGetSymbolAddress((void**)&wB2, g_wB2);
    cudaGetSymbolAddress((void**)&wB3, g_wB3);

    cudaFuncSetAttribute(conv_tc<32, 64, true>,
                         cudaFuncAttributeMaxDynamicSharedMemorySize, CONV_SMEM);
    cudaFuncSetAttribute(conv_tc<64, 60, false>,
                         cudaFuncAttributeMaxDynamicSharedMemorySize, CONV_SMEM);

    // weight reorders (tiny)
    reorder_w<<<(9 * 2048 + 255) / 256, 256>>>(w2, wB2, 32, 64, 1);
    reorder_w<<<(18 * 2048 + 255) / 256, 256>>>(w3, wB3, 64, 60, 2);

    // conv1: 10 -> 32, scalar fp32
    conv3x3_kernel<10, 32, true><<<dim3(8, 8, 4 * 2), dim3(16, 16)>>>(x, w1, p1);
    // conv2: 32 -> 64, 3xTF32 mma.sync (relu on input)
    conv_tc<32, 64, true><<<dim3(2, 256, 4), 256, CONV_SMEM>>>(p1, wB2, p2);
    // conv3: 64 -> 60, 3xTF32 mma.sync
    conv_tc<64, 60, false><<<dim3(2, 256, 4), 256, CONV_SMEM>>>(p2, wB3, pm);
    // fused guide + PAC epilogue (also zeroes frame 9)
    fuse_kernel<<<dim3(8, 32, 40), dim3(32, 8)>>>(x, pm, pw, pb, out);
}